// round 9
// baseline (speedup 1.0000x reference)
#include <cuda_runtime.h>
#include <math.h>

#define HW   256
#define EPS  1e-9f
#define WPB  8     // warps (batch rows) per block

// FTZ fp32 ops — the reference is XLA-GPU-compiled (ftz=true); subnormal
// flushing during the scan is load-bearing (it erodes the count support and
// sets the KL-plateau onset per row).
__device__ __forceinline__ float fmul_ftz(float a, float b) {
    float c; asm("mul.ftz.f32 %0, %1, %2;" : "=f"(c) : "f"(a), "f"(b)); return c;
}
__device__ __forceinline__ float fadd_ftz(float a, float b) {
    float c; asm("add.ftz.f32 %0, %1, %2;" : "=f"(c) : "f"(a), "f"(b)); return c;
}
__device__ __forceinline__ float fsub_ftz(float a, float b) {
    float c; asm("sub.ftz.f32 %0, %1, %2;" : "=f"(c) : "f"(a), "f"(b)); return c;
}
__device__ __forceinline__ float fdiv_ftz(float a, float b) {
    float c; asm("div.rn.ftz.f32 %0, %1, %2;" : "=f"(c) : "f"(a), "f"(b)); return c;
}

// One warp per batch row. Lane L owns count-support slots s = L (c0) and
// s = L + 32 (c1). Slots s >= 42 are exactly zero from step 0 (cd0 underflow
// under FTZ) and zeros are absorbing, so 64 slots cover the 257-wide support.
__global__ __launch_bounds__(WPB * 32)
void spair_obj_kl_kernel(const float* __restrict__ z_pres,
                         const float* __restrict__ z_pres_prob,
                         float* __restrict__ out, int B)
{
    __shared__ float s_samp[WPB][HW];
    __shared__ float s_prob[WPB][HW];
    __shared__ float s_lp[WPB][HW];
    __shared__ float s_lq[WPB][HW];

    const int warp = threadIdx.x >> 5;
    const int lane = threadIdx.x & 31;
    const int b    = blockIdx.x * WPB + warp;
    if (b >= B) return;

    const float* zp = z_pres      + (size_t)b * HW;
    const float* pp = z_pres_prob + (size_t)b * HW;
    float*       o  = out         + (size_t)b * HW;

    // ---- stage inputs: rounded samples, probs, hoisted safe-logs ----
#pragma unroll
    for (int j = 0; j < 8; ++j) {
        const int idx = lane + 32 * j;
        const float pr = pp[idx];
        s_samp[warp][idx] = rintf(zp[idx]);            // jnp.round
        s_prob[warp][idx] = pr;
        s_lp[warp][idx]   = logf(pr + EPS);
        s_lq[warp][idx]   = logf(1.0f - pr + EPS);
    }

    // ---- initial geometric count distribution (FTZ: flush subnormals) ----
    // p as the reference computes it in fp32; powers via double pow cast to
    // fp32 (normal-range values are ulp-identical to fp32 pow), then FTZ:
    // s <= 41 normal and kept, s >= 42 subnormal -> exact 0.
    const float  p_f    = 1.0f / (expf(2.0f) + 1.0f);
    const double base_d = (double)p_f;
    const double omp_d  = 1.0 - base_d;

    const int s1v = lane + 32;
    float c0 = (float)(omp_d * pow(base_d, (double)lane));
    float c1 = (float)(omp_d * pow(base_d, (double)s1v));
    if (fabsf(c0) < 1.17549435e-38f) c0 = 0.0f;        // FTZ of cd0
    if (fabsf(c1) < 1.17549435e-38f) c1 = 0.0f;

    float acc = fadd_ftz(c0, c1);
#pragma unroll
    for (int off = 16; off; off >>= 1)
        acc = fadd_ftz(acc, __shfl_xor_sync(0xffffffffu, acc, off));
    c0 = fdiv_ftz(c0, acc);
    c1 = fdiv_ftz(c1, acc);

    __syncwarp();

    const float sf0 = (float)lane;
    const float sf1 = (float)s1v;

    // ---- sequential scan (live region) ----
    float csf  = 0.0f;              // count_so_far (warp-uniform, exact int)
    int   i    = 0;
    bool  dead = false;
#pragma unroll 1
    for (; i < HW; ++i) {
        const float sample = s_samp[warp][i];
        const bool  is_one = sample > 0.5f;
        const float denom  = (float)(HW - i);

        // v = clip(s - csf, 0, denom) / denom  (subs exact: small integers)
        const float v0 = fdiv_ftz(fminf(fmaxf(fsub_ftz(sf0, csf), 0.0f), denom), denom);
        const float v1 = fdiv_ftz(fminf(fmaxf(fsub_ftz(sf1, csf), 0.0f), denom), denom);

        // p_z terms (old cd * v) and cd update (old cd * mult) — FTZ products
        // are where support erosion happens.
        const float pz0 = fmul_ftz(c0, v0);
        const float pz1 = fmul_ftz(c1, v1);
        const float m0  = is_one ? v0 : fsub_ftz(1.0f, v0);
        const float m1  = is_one ? v1 : fsub_ftz(1.0f, v1);
        const float u0  = fmul_ftz(c0, m0);
        const float u1  = fmul_ftz(c1, m1);

        float psum = fadd_ftz(pz0, pz1);
        float nsum = fadd_ftz(u0, u1);
        // interleaved butterfly: two independent reductions share one tree
#pragma unroll
        for (int off = 16; off; off >>= 1) {
            psum = fadd_ftz(psum, __shfl_xor_sync(0xffffffffu, psum, off));
            nsum = fadd_ftz(nsum, __shfl_xor_sync(0xffffffffu, nsum, off));
        }

        const float p_z  = psum;                     // exact 0 once support <= csf
        const float norm = fmaxf(nsum, 1e-6f);       // jnp.clip(., 1e-6, None)

        // KL for step i (warp-uniform; lane 0 stores)
        const float pr = s_prob[warp][i];
        const float kl = pr * (s_lp[warp][i] - logf(p_z + EPS))
                       + (1.0f - pr) * (s_lq[warp][i] - logf((1.0f - p_z) + EPS));
        if (lane == 0) o[i] = kl;

        if (nsum == 0.0f) { dead = true; ++i; break; }   // absorbing collapse

        // end-of-step normalization (ref: cd1 / norm), FTZ division
        c0  = fdiv_ftz(u0, norm);
        c1  = fdiv_ftz(u1, norm);
        csf = fadd_ftz(csf, sample);
    }

    // ---- dead tail: p_z == 0 exactly for all remaining steps (parallel) ----
    if (dead) {
        const float lpz_dead = logf(0.0f + EPS);     // log(1e-9)
        // log(1 - 0 + EPS): 1.0f + 1e-9f rounds to 1.0f -> log == 0
        for (int idx = i + lane; idx < HW; idx += 32) {
            const float pr = s_prob[warp][idx];
            o[idx] = pr * (s_lp[warp][idx] - lpz_dead)
                   + (1.0f - pr) * s_lq[warp][idx];
        }
    }
}

extern "C" void kernel_launch(void* const* d_in, const int* in_sizes, int n_in,
                              void* d_out, int out_size)
{
    const float* z_pres      = (const float*)d_in[0];
    const float* z_pres_prob = (const float*)d_in[1];
    float*       out         = (float*)d_out;

    const int B = in_sizes[0] / HW;                  // 1024
    const int blocks = (B + WPB - 1) / WPB;
    spair_obj_kl_kernel<<<blocks, WPB * 32>>>(z_pres, z_pres_prob, out, B);
}

// round 10
// speedup vs baseline: 1.1946x; 1.1946x over previous
#include <cuda_runtime.h>
#include <math.h>

#define HW    256
#define EPS   1e-9f
#define WPB   4      // warps (batch rows) per block
#define KPAD  43     // v-table k range [0,42]; live support caps at s=41

// FTZ fp32 ops — reference is XLA-GPU-compiled (ftz=true); subnormal flushing
// during the scan erodes the count support and sets the KL-plateau onset.
__device__ __forceinline__ float fmul_ftz(float a, float b) {
    float c; asm("mul.ftz.f32 %0, %1, %2;" : "=f"(c) : "f"(a), "f"(b)); return c;
}
__device__ __forceinline__ float fadd_ftz(float a, float b) {
    float c; asm("add.ftz.f32 %0, %1, %2;" : "=f"(c) : "f"(a), "f"(b)); return c;
}
__device__ __forceinline__ float fsub_ftz(float a, float b) {
    float c; asm("sub.ftz.f32 %0, %1, %2;" : "=f"(c) : "f"(a), "f"(b)); return c;
}
__device__ __forceinline__ float fdiv_ftz(float a, float b) {
    float c; asm("div.rn.ftz.f32 %0, %1, %2;" : "=f"(c) : "f"(a), "f"(b)); return c;
}

__global__ __launch_bounds__(WPB * 32)
void spair_obj_kl_kernel(const float* __restrict__ z_pres,
                         const float* __restrict__ z_pres_prob,
                         float* __restrict__ out, int B)
{
    // v-table: T[i*KPAD + k] = div.rn.ftz(min(k, 256-i), 256-i) — the exact
    // same instruction/operands the scan used per-step in the 98.8us version,
    // hoisted and shared by the whole block. 44 KB.
    __shared__ float    s_T[HW * KPAD];
    __shared__ float    s_pz[WPB][HW];       // p_z per step (scan -> epilogue)
    __shared__ unsigned s_bits[WPB][HW / 32];// rounded z_pres as bitmask

    const int tid  = threadIdx.x;
    const int warp = tid >> 5;
    const int lane = tid & 31;
    const int b    = blockIdx.x * WPB + warp;

    // ---- cooperative v-table build (all threads, before the row guard) ----
    for (int e = tid; e < HW * KPAD; e += WPB * 32) {
        const int i = e / KPAD;
        const int k = e - i * KPAD;
        const int d = HW - i;
        s_T[e] = fdiv_ftz((float)(k < d ? k : d), (float)d);
    }

    if (b < B) {
        const float* zp = z_pres + (size_t)b * HW;
        unsigned bit = 0;
#pragma unroll
        for (int j = 0; j < 8; ++j)
            bit |= (rintf(zp[32 * j + lane]) > 0.5f) ? (1u << j) : 0u;
        // lane L collects bit j for step 32*j+L -> transpose via ballot
#pragma unroll
        for (int j = 0; j < 8; ++j) {
            const unsigned w = __ballot_sync(0xffffffffu, (bit >> j) & 1u);
            if (lane == j) s_bits[warp][j] = w;
        }
    }
    __syncthreads();
    if (b >= B) return;

    const float* pp = z_pres_prob + (size_t)b * HW;
    float*       o  = out         + (size_t)b * HW;

    // ---- initial geometric count distribution (FTZ flushes s >= 42) ----
    const float  p_f    = 1.0f / (expf(2.0f) + 1.0f);
    const double base_d = (double)p_f;
    const double omp_d  = 1.0 - base_d;

    const int s1v = lane + 32;
    float c0 = (float)(omp_d * pow(base_d, (double)lane));
    float c1 = (float)(omp_d * pow(base_d, (double)s1v));
    if (fabsf(c0) < 1.17549435e-38f) c0 = 0.0f;
    if (fabsf(c1) < 1.17549435e-38f) c1 = 0.0f;

    float acc = fadd_ftz(c0, c1);
#pragma unroll
    for (int off = 16; off; off >>= 1)
        acc = fadd_ftz(acc, __shfl_xor_sync(0xffffffffu, acc, off));
    c0 = fdiv_ftz(c0, acc);
    c1 = fdiv_ftz(c1, acc);

    // ---- sequential scan (live region): identical trajectory arithmetic ----
    int csf   = 0;        // count_so_far, exact integer
    int i     = 0;
    int i_end = HW;       // first step index past the recorded p_z values
#pragma unroll 1
    for (; i < HW; ++i) {
        const unsigned wbits  = s_bits[warp][i >> 5];
        const bool     is_one = (wbits >> (i & 31)) & 1u;

        // v from the table: bit-identical to clip(s-csf,0,d)/d via div.rn.ftz
        int k0 = lane - csf;        k0 = k0 < 0 ? 0 : (k0 > 42 ? 42 : k0);
        int k1 = lane + 32 - csf;   k1 = k1 < 0 ? 0 : (k1 > 42 ? 42 : k1);
        const float v0 = s_T[i * KPAD + k0];   // dead slots (cd==0) read a
        const float v1 = s_T[i * KPAD + k1];   // clamped v; 0*v == 0 anyway

        const float pz0 = fmul_ftz(c0, v0);
        const float pz1 = fmul_ftz(c1, v1);
        const float m0  = is_one ? v0 : fsub_ftz(1.0f, v0);
        const float m1  = is_one ? v1 : fsub_ftz(1.0f, v1);
        const float u0  = fmul_ftz(c0, m0);
        const float u1  = fmul_ftz(c1, m1);

        float psum = fadd_ftz(pz0, pz1);
        float nsum = fadd_ftz(u0, u1);
#pragma unroll
        for (int off = 16; off; off >>= 1) {
            psum = fadd_ftz(psum, __shfl_xor_sync(0xffffffffu, psum, off));
            nsum = fadd_ftz(nsum, __shfl_xor_sync(0xffffffffu, nsum, off));
        }

        if (lane == 0) s_pz[warp][i] = psum;   // KL deferred to epilogue

        if (nsum == 0.0f) { i_end = i + 1; break; }   // absorbing collapse

        const float norm = fmaxf(nsum, 1e-6f);
        c0 = fdiv_ftz(u0, norm);
        c1 = fdiv_ftz(u1, norm);
        csf += is_one ? 1 : 0;
    }

    __syncwarp();

    // ---- epilogue: KL for all 256 steps in parallel (p_z = 0 after death) ----
#pragma unroll
    for (int j = 0; j < 8; ++j) {
        const int   idx = 32 * j + lane;
        const float pz  = (idx < i_end) ? s_pz[warp][idx] : 0.0f;
        const float pr  = pp[idx];
        const float kl  = pr * (logf(pr + EPS) - logf(pz + EPS))
                        + (1.0f - pr) * (logf(1.0f - pr + EPS)
                                         - logf((1.0f - pz) + EPS));
        o[idx] = kl;
    }
}

extern "C" void kernel_launch(void* const* d_in, const int* in_sizes, int n_in,
                              void* d_out, int out_size)
{
    const float* z_pres      = (const float*)d_in[0];
    const float* z_pres_prob = (const float*)d_in[1];
    float*       out         = (float*)d_out;

    const int B = in_sizes[0] / HW;                  // 1024
    const int blocks = (B + WPB - 1) / WPB;          // 256 -> every SM busy
    spair_obj_kl_kernel<<<blocks, WPB * 32>>>(z_pres, z_pres_prob, out, B);
}